// round 10
// baseline (speedup 1.0000x reference)
#include <cuda_runtime.h>
#include <cuda_bf16.h>
#include <cstdint>

#define B_S   256
#define P_N   64
#define V_N   2562
#define VPAD  2688          // 21*128, zero-padded tail rows
#define KP    640           // K' = 3*192 + 64 (trans chunk)
#define NCH   10            // K chunks of 64 bf16 (128B rows)
#define M_T   128           // v rows per CTA
#define N_T   64            // n cols per CTA (one i, 64 bs)

#define NDEF  81            // defsplit blocks (v-tiles of 32)
#define NROT  128           // rot blocks (2 bs each)

// ---- scratch (zero-initialized device globals; no runtime alloc) ----
__device__ __align__(16) __nv_bfloat16 g_def[(size_t)VPAD * KP];     // ~3.4MB
__device__ __align__(16) __nv_bfloat16 g_B[(size_t)3 * B_S * KP];    // ~1MB

__device__ __forceinline__ uint32_t smem_u32(const void* p) {
    uint32_t a;
    asm("{ .reg .u64 t; cvta.to.shared.u64 t, %1; cvt.u32.u64 %0, t; }" : "=r"(a) : "l"(p));
    return a;
}
__device__ __forceinline__ uint32_t sw128(uint32_t x) { return x ^ ((x >> 3) & 0x70); }

#define LDSM4(r, addr) \
    asm volatile("ldmatrix.sync.aligned.m8n8.x4.shared.b16 {%0,%1,%2,%3}, [%4];" \
        : "=r"((r)[0]), "=r"((r)[1]), "=r"((r)[2]), "=r"((r)[3]) : "r"(addr))

#define MMA(d, a, b0, b1) \
    asm volatile("mma.sync.aligned.m16n8k16.row.col.f32.bf16.bf16.f32 " \
        "{%0,%1,%2,%3}, {%4,%5,%6,%7}, {%8,%9}, {%0,%1,%2,%3};" \
        : "+f"((d)[0]), "+f"((d)[1]), "+f"((d)[2]), "+f"((d)[3]) \
        : "r"((a)[0]), "r"((a)[1]), "r"((a)[2]), "r"((a)[3]), "r"(b0), "r"(b1))

// ---------------------------------------------------------------------------
// Fused prep. Blocks [0, NDEF): defsplit (v-tile of 32, smem transpose).
// Blocks [NDEF, NDEF+NROT): rot — 2 bs per block, builds B-hat rows.
// ---------------------------------------------------------------------------
#define PREP_SMEM (32 * KP * 2 + 512)   // 40KB row staging + base staging

__global__ __launch_bounds__(128) void prep_kernel(
    const float* __restrict__ off,        // (P,V,3)
    const float* __restrict__ base,       // (V,3)
    const float* __restrict__ scales,     // (B,S,1)
    const float* __restrict__ transforms, // (B,S,P,6)
    const float* __restrict__ pw)         // (B,S,P)
{
    extern __shared__ __align__(16) char smem[];
    const int tid = threadIdx.x;

    if (blockIdx.x < NDEF) {
        // ================= defsplit branch =================
        __nv_bfloat16* s_row = (__nv_bfloat16*)smem;      // [32][KP]
        float* s_base = (float*)(smem + 32 * KP * 2);     // [96]
        const int v0 = blockIdx.x * 32;
        const bool fullt = (v0 + 32 <= V_N);

        // zero rows + stage base slice
        #pragma unroll
        for (int i = 0; i < 20; ++i)
            ((uint4*)s_row)[tid + i * 128] = make_uint4(0, 0, 0, 0);
        if (tid < 96) {
            const int gi = v0 * 3 + tid;
            s_base[tid] = (gi < V_N * 3) ? base[gi] : 0.f;
        }
        __syncthreads();

        // scatter: 64 p x 48 float2 per p (96 floats = 32v x 3j)
        for (int idx = tid; idx < P_N * 48; idx += 128) {
            const int p = idx / 48, q = idx - p * 48;
            const int f0 = q * 2;
            float e[2];
            if (fullt) {
                const float2 d = *(const float2*)(off + ((size_t)p * V_N + v0) * 3 + f0);
                e[0] = d.x; e[1] = d.y;
            } else {
                #pragma unroll
                for (int t = 0; t < 2; ++t) {
                    const int f = f0 + t;
                    e[t] = (v0 + f / 3 < V_N)
                         ? off[((size_t)p * V_N + v0) * 3 + f] : 0.f;
                }
            }
            #pragma unroll
            for (int t = 0; t < 2; ++t) {
                const int f = f0 + t;
                const int vl = f / 3, j = f - 3 * vl;
                const int k = p * 3 + j;
                const float d = e[t] + s_base[f];
                const __nv_bfloat16 hi = __float2bfloat16(d);
                const __nv_bfloat16 lo = __float2bfloat16(d - __bfloat162float(hi));
                __nv_bfloat16* row = s_row + vl * KP;
                row[k] = hi; row[192 + k] = lo; row[384 + k] = hi;
            }
        }
        // trans chunk ones
        if (tid < 32) {
            s_row[tid * KP + 576] = __float2bfloat16(1.0f);
            s_row[tid * KP + 577] = __float2bfloat16(1.0f);
        }
        __syncthreads();

        // coalesced write-out: 32 rows x 80 uint4
        #pragma unroll
        for (int i = 0; i < 20; ++i) {
            const int idx = tid + i * 128;
            const int row = idx / 80, u = idx - row * 80;
            *(uint4*)(g_def + ((size_t)(v0 + row) * KP) + u * 8) =
                ((const uint4*)(s_row + row * KP))[u];
        }
    } else {
        // ================= rot branch (2 bs per block) =================
        const int bs = (blockIdx.x - NDEF) * 2 + (tid >> 6);
        const int p  = tid & 63;

        const float* t = transforms + ((size_t)bs * P_N + p) * 6;
        const float w  = pw[bs * P_N + p];
        const float ws = w * scales[bs];

        float sx, cx, sy, cy, sz, cz;
        sincosf(t[3], &sx, &cx);
        sincosf(t[4], &sy, &cy);
        sincosf(t[5], &sz, &cz);

        float m[9];
        m[0] = cy*cz;            m[1] = -cy*sz;           m[2] = sy;
        m[3] = cx*sz + sx*sy*cz; m[4] = cx*cz - sx*sy*sz; m[5] = -sx*cy;
        m[6] = sx*sz - cx*sy*cz; m[7] = sx*cz + cx*sy*sz; m[8] = cx*cy;

        #pragma unroll
        for (int i = 0; i < 3; ++i) {
            __nv_bfloat16* row = g_B + ((size_t)i * B_S + bs) * KP;
            #pragma unroll
            for (int j = 0; j < 3; ++j) {
                const float val = m[i * 3 + j] * ws;
                const __nv_bfloat16 hi = __float2bfloat16(val);
                const __nv_bfloat16 lo = __float2bfloat16(val - __bfloat162float(hi));
                const int k = p * 3 + j;
                row[k] = hi; row[192 + k] = hi; row[384 + k] = lo;
            }
        }

        float* red = (float*)smem;   // [128][4]
        red[tid * 4 + 0] = w * t[0];
        red[tid * 4 + 1] = w * t[1];
        red[tid * 4 + 2] = w * t[2];
        __syncthreads();
        if (p < 3) {
            const int b0 = (tid >> 6) * 64;
            float s = 0.f;
            for (int q = 0; q < 64; ++q) s += red[(b0 + q) * 4 + p];
            const __nv_bfloat16 hi = __float2bfloat16(s);
            const __nv_bfloat16 lo = __float2bfloat16(s - __bfloat162float(hi));
            __nv_bfloat16* row = g_B + ((size_t)p * B_S + bs) * KP;
            row[576] = hi; row[577] = lo;
        }
    }
}

// ---------------------------------------------------------------------------
// Main GEMM via mma.sync (HMMA): C[v, n] = A-hat @ B-hat^T, per-CTA 128x64,
// K'=640. Grid (21, 12): blockIdx.y -> (i = y/4, bs quarter = y%4). 8 warps
// 4x2, warp = 32x32. Double-buffered 64-wide K chunks, SW128-swizzled smem.
// 2 CTAs/SM, one wave.
// ---------------------------------------------------------------------------
#define SM_A(b)   ((b) * 24576u)             // 16KB A tile
#define SM_B(b)   ((b) * 24576u + 16384u)    // 8KB  B tile
#define SMEM_BYTES 49152

__global__ __launch_bounds__(256, 2) void mesh_gemm_kernel(float* __restrict__ out)
{
    extern __shared__ __align__(1024) char smem[];
    const uint32_t sbase = smem_u32(smem);
    const int tid  = threadIdx.x;
    const int lane = tid & 31;
    const int warp = tid >> 5;
    const int v0   = blockIdx.x * M_T;
    const int nb   = blockIdx.y;
    const int i_   = nb >> 2;                  // output component
    const int bs0  = (nb & 3) * N_T;           // bs quarter base
    const int bRow0 = i_ * B_S + bs0;          // g_B row base

    const int wm = warp & 3;                   // warp row (4) -> 32 v
    const int wn = warp >> 2;                  // warp col (2) -> 32 n

    const int rowA  = wm * 32 + (lane & 7) + ((lane >> 3) & 1) * 8;
    const int kselA = ((lane >> 4) & 1) * 16;
    const int rowB  = wn * 32 + ((lane >> 4) & 1) * 8 + (lane & 7);
    const int kselB = ((lane >> 3) & 1) * 16;

    float acc[2][4][4];
    #pragma unroll
    for (int mt = 0; mt < 2; ++mt)
        #pragma unroll
        for (int nt = 0; nt < 4; ++nt)
            #pragma unroll
            for (int e = 0; e < 4; ++e) acc[mt][nt][e] = 0.f;

    uint4 st[6];
    auto ldg_chunk = [&](int c) {
        #pragma unroll
        for (int it = 0; it < 4; ++it) {
            const int jdx = tid + it * 256;
            const int row = jdx >> 3, u = jdx & 7;
            st[it] = *(const uint4*)(g_def + ((size_t)(v0 + row) * KP + c * 64 + u * 8));
        }
        #pragma unroll
        for (int it = 0; it < 2; ++it) {
            const int jdx = tid + it * 256;
            const int row = jdx >> 3, u = jdx & 7;
            st[4 + it] = *(const uint4*)(g_B + ((size_t)(bRow0 + row) * KP + c * 64 + u * 8));
        }
    };
    auto sts_chunk = [&](int b) {
        #pragma unroll
        for (int it = 0; it < 4; ++it) {
            const int jdx = tid + it * 256;
            const int row = jdx >> 3, u = jdx & 7;
            *(uint4*)(smem + SM_A(b) + sw128(row * 128 + u * 16)) = st[it];
        }
        #pragma unroll
        for (int it = 0; it < 2; ++it) {
            const int jdx = tid + it * 256;
            const int row = jdx >> 3, u = jdx & 7;
            *(uint4*)(smem + SM_B(b) + sw128(row * 128 + u * 16)) = st[4 + it];
        }
    };
    auto compute = [&](int b) {
        const uint32_t sA = sbase + SM_A(b);
        const uint32_t sB = sbase + SM_B(b);
        #pragma unroll
        for (int ks = 0; ks < 4; ++ks) {
            uint32_t a0[4], a1[4], q0[4], q1[4];
            LDSM4(a0, sA + sw128(rowA * 128 + ks * 32 + kselA));
            LDSM4(a1, sA + sw128((rowA + 16) * 128 + ks * 32 + kselA));
            LDSM4(q0, sB + sw128(rowB * 128 + ks * 32 + kselB));
            LDSM4(q1, sB + sw128((rowB + 16) * 128 + ks * 32 + kselB));
            MMA(acc[0][0], a0, q0[0], q0[1]);  MMA(acc[0][1], a0, q0[2], q0[3]);
            MMA(acc[0][2], a0, q1[0], q1[1]);  MMA(acc[0][3], a0, q1[2], q1[3]);
            MMA(acc[1][0], a1, q0[0], q0[1]);  MMA(acc[1][1], a1, q0[2], q0[3]);
            MMA(acc[1][2], a1, q1[0], q1[1]);  MMA(acc[1][3], a1, q1[2], q1[3]);
        }
    };

    ldg_chunk(0); sts_chunk(0);
    __syncthreads();

    for (int c = 0; c < NCH; ++c) {
        const bool more = (c + 1 < NCH);
        if (more) ldg_chunk(c + 1);
        compute(c & 1);
        if (more) sts_chunk((c + 1) & 1);
        __syncthreads();
    }

    // ---- epilogue: scatter stores ----
    const int g  = lane >> 2;
    const int cq = lane & 3;
    #pragma unroll
    for (int mt = 0; mt < 2; ++mt) {
        const int vA = v0 + wm * 32 + mt * 16 + g;
        const int vB = vA + 8;
        #pragma unroll
        for (int nt = 0; nt < 4; ++nt) {
            const int bs = bs0 + wn * 32 + nt * 8 + 2 * cq;
            const size_t r0 = ((size_t)bs * V_N) * 3 + i_;
            const size_t r1 = ((size_t)(bs + 1) * V_N) * 3 + i_;
            if (vA < V_N) {
                out[r0 + (size_t)vA * 3] = acc[mt][nt][0];
                out[r1 + (size_t)vA * 3] = acc[mt][nt][1];
            }
            if (vB < V_N) {
                out[r0 + (size_t)vB * 3] = acc[mt][nt][2];
                out[r1 + (size_t)vB * 3] = acc[mt][nt][3];
            }
        }
    }
}

// ---------------------------------------------------------------------------
extern "C" void kernel_launch(void* const* d_in, const int* in_sizes, int n_in,
                              void* d_out, int out_size)
{
    (void)in_sizes; (void)n_in; (void)out_size;
    const float* scales     = (const float*)d_in[0];  // (B,S,1)
    const float* transforms = (const float*)d_in[1];  // (B,S,P,6)
    const float* pw         = (const float*)d_in[2];  // (B,S,P)
    const float* off        = (const float*)d_in[3];  // (P,V,3)
    const float* base       = (const float*)d_in[4];  // (V,3)
    float* out = (float*)d_out;

    cudaFuncSetAttribute(prep_kernel,
                         cudaFuncAttributeMaxDynamicSharedMemorySize, PREP_SMEM);
    prep_kernel<<<NDEF + NROT, 128, PREP_SMEM>>>(off, base, scales, transforms, pw);

    cudaFuncSetAttribute(mesh_gemm_kernel,
                         cudaFuncAttributeMaxDynamicSharedMemorySize, SMEM_BYTES);
    dim3 grid((V_N + M_T - 1) / M_T, 12);   // (21, 12) = 252 CTAs
    mesh_gemm_kernel<<<grid, 256, SMEM_BYTES>>>(out);
}

// round 11
// speedup vs baseline: 1.3720x; 1.3720x over previous
#include <cuda_runtime.h>
#include <cuda_bf16.h>
#include <cstdint>

#define B_S   256
#define P_N   64
#define V_N   2562
#define VPAD  2688          // 21*128, zero-padded tail rows
#define KP    640           // K' = 3*192 + 64 (trans chunk)
#define NCH   10            // K chunks of 64 bf16 (128B rows)
#define M_T   128           // v rows per CTA
#define N_T   64            // n cols per CTA (one i, 64 bs)

#define VTP   8             // defsplit v-tile
#define NDEF  321           // ceil(2562/8)
#define NROT  128           // rot blocks (2 bs each)
#define ROWS  648           // padded smem row stride (bf16) to break bank pattern

// ---- scratch (zero-initialized device globals; no runtime alloc) ----
__device__ __align__(16) __nv_bfloat16 g_def[(size_t)VPAD * KP];     // ~3.4MB
__device__ __align__(16) __nv_bfloat16 g_B[(size_t)3 * B_S * KP];    // ~1MB

__device__ __forceinline__ uint32_t smem_u32(const void* p) {
    uint32_t a;
    asm("{ .reg .u64 t; cvta.to.shared.u64 t, %1; cvt.u32.u64 %0, t; }" : "=r"(a) : "l"(p));
    return a;
}
__device__ __forceinline__ uint32_t sw128(uint32_t x) { return x ^ ((x >> 3) & 0x70); }

#define CP16(dst, src) \
    asm volatile("cp.async.cg.shared.global [%0], [%1], 16;" :: "r"(dst), "l"(src))
#define CP_COMMIT() asm volatile("cp.async.commit_group;" ::: "memory")
#define CP_WAIT1()  asm volatile("cp.async.wait_group 1;" ::: "memory")

#define LDSM4(r, addr) \
    asm volatile("ldmatrix.sync.aligned.m8n8.x4.shared.b16 {%0,%1,%2,%3}, [%4];" \
        : "=r"((r)[0]), "=r"((r)[1]), "=r"((r)[2]), "=r"((r)[3]) : "r"(addr))

#define MMA(d, a, b0, b1) \
    asm volatile("mma.sync.aligned.m16n8k16.row.col.f32.bf16.bf16.f32 " \
        "{%0,%1,%2,%3}, {%4,%5,%6,%7}, {%8,%9}, {%0,%1,%2,%3};" \
        : "+f"((d)[0]), "+f"((d)[1]), "+f"((d)[2]), "+f"((d)[3]) \
        : "r"((a)[0]), "r"((a)[1]), "r"((a)[2]), "r"((a)[3]), "r"(b0), "r"(b1))

// ---------------------------------------------------------------------------
// Fused prep. Blocks [0, NDEF): defsplit (v-tile of 8, coalesced transpose).
// Blocks [NDEF, NDEF+NROT): rot — 2 bs per block, builds B-hat rows.
// ---------------------------------------------------------------------------
#define PREP_SMEM (VTP * ROWS * 2 + 128)

__global__ __launch_bounds__(128) void prep_kernel(
    const float* __restrict__ off,        // (P,V,3)
    const float* __restrict__ base,       // (V,3)
    const float* __restrict__ scales,     // (B,S,1)
    const float* __restrict__ transforms, // (B,S,P,6)
    const float* __restrict__ pw)         // (B,S,P)
{
    extern __shared__ __align__(16) char smem[];
    const int tid = threadIdx.x;

    if (blockIdx.x < NDEF) {
        // ================= defsplit branch =================
        __nv_bfloat16* s_row = (__nv_bfloat16*)smem;        // [VTP][ROWS]
        float* s_base = (float*)(smem + VTP * ROWS * 2);    // [24]
        const int v0 = blockIdx.x * VTP;
        const int nv3 = min(VTP * 3, (V_N - v0) * 3);

        // zero rows (648 uint4 total)
        for (int i = tid; i < (VTP * ROWS) / 8; i += 128)
            ((uint4*)s_row)[i] = make_uint4(0, 0, 0, 0);
        if (tid < VTP * 3)
            s_base[tid] = (v0 * 3 + tid < V_N * 3) ? base[v0 * 3 + tid] : 0.f;
        __syncthreads();

        // coalesced read + transpose: 64 p x 12 float2 (24 floats = 8v x 3j)
        for (int idx = tid; idx < P_N * 12; idx += 128) {
            const int p = idx / 12, q = idx - p * 12;
            const int f0 = 2 * q;
            float e[2];
            if (f0 + 1 < nv3) {
                const float2 d = *(const float2*)(off + ((size_t)p * V_N + v0) * 3 + f0);
                e[0] = d.x; e[1] = d.y;
            } else {
                e[0] = (f0 < nv3) ? off[((size_t)p * V_N + v0) * 3 + f0] : 0.f;
                e[1] = 0.f;
            }
            #pragma unroll
            for (int t = 0; t < 2; ++t) {
                const int f = f0 + t;
                const int vl = f / 3, j = f - 3 * vl;
                const int k = p * 3 + j;
                const float d = e[t] + s_base[f];
                const __nv_bfloat16 hi = __float2bfloat16(d);
                const __nv_bfloat16 lo = __float2bfloat16(d - __bfloat162float(hi));
                __nv_bfloat16* row = s_row + vl * ROWS;
                row[k] = hi; row[192 + k] = lo; row[384 + k] = hi;
            }
        }
        if (tid < VTP) {
            s_row[tid * ROWS + 576] = __float2bfloat16(1.0f);
            s_row[tid * ROWS + 577] = __float2bfloat16(1.0f);
        }
        __syncthreads();

        // coalesced write-out: 8 rows x 80 uint4
        for (int i = tid; i < VTP * 80; i += 128) {
            const int row = i / 80, u = i - row * 80;
            *(uint4*)(g_def + (size_t)(v0 + row) * KP + u * 8) =
                ((const uint4*)(s_row + row * ROWS))[u];
        }
    } else {
        // ================= rot branch (2 bs per block) =================
        const int bs = (blockIdx.x - NDEF) * 2 + (tid >> 6);
        const int p  = tid & 63;

        const float* t = transforms + ((size_t)bs * P_N + p) * 6;
        const float w  = pw[bs * P_N + p];
        const float ws = w * scales[bs];

        float sx, cx, sy, cy, sz, cz;
        sincosf(t[3], &sx, &cx);
        sincosf(t[4], &sy, &cy);
        sincosf(t[5], &sz, &cz);

        float m[9];
        m[0] = cy*cz;            m[1] = -cy*sz;           m[2] = sy;
        m[3] = cx*sz + sx*sy*cz; m[4] = cx*cz - sx*sy*sz; m[5] = -sx*cy;
        m[6] = sx*sz - cx*sy*cz; m[7] = sx*cz + cx*sy*sz; m[8] = cx*cy;

        #pragma unroll
        for (int i = 0; i < 3; ++i) {
            __nv_bfloat16* row = g_B + ((size_t)i * B_S + bs) * KP;
            #pragma unroll
            for (int j = 0; j < 3; ++j) {
                const float val = m[i * 3 + j] * ws;
                const __nv_bfloat16 hi = __float2bfloat16(val);
                const __nv_bfloat16 lo = __float2bfloat16(val - __bfloat162float(hi));
                const int k = p * 3 + j;
                row[k] = hi; row[192 + k] = hi; row[384 + k] = lo;
            }
        }

        float* red = (float*)smem;   // [128][4]
        red[tid * 4 + 0] = w * t[0];
        red[tid * 4 + 1] = w * t[1];
        red[tid * 4 + 2] = w * t[2];
        __syncthreads();
        if (p < 3) {
            const int b0 = (tid >> 6) * 64;
            float s = 0.f;
            for (int q = 0; q < 64; ++q) s += red[(b0 + q) * 4 + p];
            const __nv_bfloat16 hi = __float2bfloat16(s);
            const __nv_bfloat16 lo = __float2bfloat16(s - __bfloat162float(hi));
            __nv_bfloat16* row = g_B + ((size_t)p * B_S + bs) * KP;
            row[576] = hi; row[577] = lo;
        }
    }
}

// ---------------------------------------------------------------------------
// Main GEMM via mma.sync: C[v, n] = A-hat @ B-hat^T, per-CTA 128x64, K'=640.
// 3-stage cp.async pipeline, one __syncthreads per iteration.
// Grid (21, 12), 8 warps 4x2 of 32x32 each. 2 CTAs/SM, one wave.
// ---------------------------------------------------------------------------
#define STG_SZ    24576u                      // A 16KB + B 8KB per stage
#define SM_A(b)   ((b) * STG_SZ)
#define SM_B(b)   ((b) * STG_SZ + 16384u)
#define SMEM_BYTES (3 * 24576)                // 73,728

__global__ __launch_bounds__(256, 2) void mesh_gemm_kernel(float* __restrict__ out)
{
    extern __shared__ __align__(1024) char smem[];
    const uint32_t sbase = smem_u32(smem);
    const int tid  = threadIdx.x;
    const int lane = tid & 31;
    const int warp = tid >> 5;
    const int v0   = blockIdx.x * M_T;
    const int nb   = blockIdx.y;
    const int i_   = nb >> 2;                  // output component
    const int bs0  = (nb & 3) * N_T;           // bs quarter base
    const int bRow0 = i_ * B_S + bs0;          // g_B row base

    const int wm = warp & 3;                   // warp row (4) -> 32 v
    const int wn = warp >> 2;                  // warp col (2) -> 32 n

    const int rowA  = wm * 32 + (lane & 7) + ((lane >> 3) & 1) * 8;
    const int kselA = ((lane >> 4) & 1) * 16;
    const int rowB  = wn * 32 + ((lane >> 4) & 1) * 8 + (lane & 7);
    const int kselB = ((lane >> 3) & 1) * 16;

    // per-thread staging coords (computed once)
    const int rA0 = tid >> 3, uA = (tid & 7) * 16;        // A: rows rA0, rA0+32, +64, +96
    const int rB0 = tid >> 3, uB = (tid & 7) * 16;        // B: rows rB0, rB0+32  (row < 64)

    float acc[2][4][4];
    #pragma unroll
    for (int mt = 0; mt < 2; ++mt)
        #pragma unroll
        for (int nt = 0; nt < 4; ++nt)
            #pragma unroll
            for (int e = 0; e < 4; ++e) acc[mt][nt][e] = 0.f;

    auto stage_cp = [&](int c, int b) {
        const uint32_t sA = sbase + SM_A(b), sB = sbase + SM_B(b);
        const __nv_bfloat16* gA = g_def + (size_t)v0 * KP + c * 64;
        const __nv_bfloat16* gB = g_B + (size_t)bRow0 * KP + c * 64;
        #pragma unroll
        for (int it = 0; it < 4; ++it) {
            const int row = rA0 + it * 32;
            CP16(sA + sw128(row * 128 + uA), gA + (size_t)row * KP + uA / 2);
        }
        #pragma unroll
        for (int it = 0; it < 2; ++it) {
            const int row = rB0 + it * 32;
            CP16(sB + sw128(row * 128 + uB), gB + (size_t)row * KP + uB / 2);
        }
    };
    auto compute = [&](int b) {
        const uint32_t sA = sbase + SM_A(b);
        const uint32_t sB = sbase + SM_B(b);
        #pragma unroll
        for (int ks = 0; ks < 4; ++ks) {
            uint32_t a0[4], a1[4], q0[4], q1[4];
            LDSM4(a0, sA + sw128(rowA * 128 + ks * 32 + kselA));
            LDSM4(a1, sA + sw128((rowA + 16) * 128 + ks * 32 + kselA));
            LDSM4(q0, sB + sw128(rowB * 128 + ks * 32 + kselB));
            LDSM4(q1, sB + sw128((rowB + 16) * 128 + ks * 32 + kselB));
            MMA(acc[0][0], a0, q0[0], q0[1]);  MMA(acc[0][1], a0, q0[2], q0[3]);
            MMA(acc[0][2], a0, q1[0], q1[1]);  MMA(acc[0][3], a0, q1[2], q1[3]);
            MMA(acc[1][0], a1, q0[0], q0[1]);  MMA(acc[1][1], a1, q0[2], q0[3]);
            MMA(acc[1][2], a1, q1[0], q1[1]);  MMA(acc[1][3], a1, q1[2], q1[3]);
        }
    };

    stage_cp(0, 0); CP_COMMIT();
    stage_cp(1, 1); CP_COMMIT();

    for (int c = 0; c < NCH; ++c) {
        CP_WAIT1();                 // my groups <= c complete
        __syncthreads();            // everyone's complete + compute(c-1) done
        compute(c % 3);
        if (c + 2 < NCH) stage_cp(c + 2, (c + 2) % 3);
        CP_COMMIT();                // commit (possibly empty) group each iter
    }

    // ---- epilogue: scatter stores ----
    const int g  = lane >> 2;
    const int cq = lane & 3;
    #pragma unroll
    for (int mt = 0; mt < 2; ++mt) {
        const int vA = v0 + wm * 32 + mt * 16 + g;
        const int vB = vA + 8;
        #pragma unroll
        for (int nt = 0; nt < 4; ++nt) {
            const int bs = bs0 + wn * 32 + nt * 8 + 2 * cq;
            const size_t r0 = ((size_t)bs * V_N) * 3 + i_;
            const size_t r1 = ((size_t)(bs + 1) * V_N) * 3 + i_;
            if (vA < V_N) {
                out[r0 + (size_t)vA * 3] = acc[mt][nt][0];
                out[r1 + (size_t)vA * 3] = acc[mt][nt][1];
            }
            if (vB < V_N) {
                out[r0 + (size_t)vB * 3] = acc[mt][nt][2];
                out[r1 + (size_t)vB * 3] = acc[mt][nt][3];
            }
        }
    }
}

// ---------------------------------------------------------------------------
extern "C" void kernel_launch(void* const* d_in, const int* in_sizes, int n_in,
                              void* d_out, int out_size)
{
    (void)in_sizes; (void)n_in; (void)out_size;
    const float* scales     = (const float*)d_in[0];  // (B,S,1)
    const float* transforms = (const float*)d_in[1];  // (B,S,P,6)
    const float* pw         = (const float*)d_in[2];  // (B,S,P)
    const float* off        = (const float*)d_in[3];  // (P,V,3)
    const float* base       = (const float*)d_in[4];  // (V,3)
    float* out = (float*)d_out;

    cudaFuncSetAttribute(prep_kernel,
                         cudaFuncAttributeMaxDynamicSharedMemorySize, PREP_SMEM);
    prep_kernel<<<NDEF + NROT, 128, PREP_SMEM>>>(off, base, scales, transforms, pw);

    cudaFuncSetAttribute(mesh_gemm_kernel,
                         cudaFuncAttributeMaxDynamicSharedMemorySize, SMEM_BYTES);
    dim3 grid((V_N + M_T - 1) / M_T, 12);   // (21, 12) = 252 CTAs
    mesh_gemm_kernel<<<grid, 256, SMEM_BYTES>>>(out);
}

// round 12
// speedup vs baseline: 1.3887x; 1.0122x over previous
#include <cuda_runtime.h>
#include <cuda_bf16.h>
#include <cstdint>

#define B_S   256
#define P_N   64
#define V_N   2562
#define VPAD  2688          // 21*128, zero-padded tail rows
#define KP    640           // K' = 3*192 + 64 (trans chunk)
#define NCH   10            // K chunks of 64 bf16 (128B rows)
#define M_T   128           // v rows per CTA
#define N_T   128           // n cols per CTA (one i, half the bs)

#define VTP   8             // defsplit v-tile
#define NDEF  321           // ceil(2562/8)
#define NROT  128           // rot blocks (2 bs each)
#define ROWS  648           // padded smem row stride (bf16)

// ---- scratch (zero-initialized device globals; no runtime alloc) ----
__device__ __align__(16) __nv_bfloat16 g_def[(size_t)VPAD * KP];     // ~3.4MB
__device__ __align__(16) __nv_bfloat16 g_B[(size_t)3 * B_S * KP];    // ~1MB

__device__ __forceinline__ uint32_t smem_u32(const void* p) {
    uint32_t a;
    asm("{ .reg .u64 t; cvta.to.shared.u64 t, %1; cvt.u32.u64 %0, t; }" : "=r"(a) : "l"(p));
    return a;
}
__device__ __forceinline__ uint32_t sw128(uint32_t x) { return x ^ ((x >> 3) & 0x70); }

#define CP16(dst, src) \
    asm volatile("cp.async.cg.shared.global [%0], [%1], 16;" :: "r"(dst), "l"(src))
#define CP_COMMIT() asm volatile("cp.async.commit_group;" ::: "memory")
#define CP_WAIT1()  asm volatile("cp.async.wait_group 1;" ::: "memory")

#define LDSM4(r, addr) \
    asm volatile("ldmatrix.sync.aligned.m8n8.x4.shared.b16 {%0,%1,%2,%3}, [%4];" \
        : "=r"((r)[0]), "=r"((r)[1]), "=r"((r)[2]), "=r"((r)[3]) : "r"(addr))

#define MMA(d, a, b0, b1) \
    asm volatile("mma.sync.aligned.m16n8k16.row.col.f32.bf16.bf16.f32 " \
        "{%0,%1,%2,%3}, {%4,%5,%6,%7}, {%8,%9}, {%0,%1,%2,%3};" \
        : "+f"((d)[0]), "+f"((d)[1]), "+f"((d)[2]), "+f"((d)[3]) \
        : "r"((a)[0]), "r"((a)[1]), "r"((a)[2]), "r"((a)[3]), "r"(b0), "r"(b1))

// ---------------------------------------------------------------------------
// Fused prep. Blocks [0, NDEF): defsplit (v-tile of 8, coalesced transpose).
// Blocks [NDEF, NDEF+NROT): rot — 2 bs per block, builds B-hat rows.
// ---------------------------------------------------------------------------
#define PREP_SMEM (VTP * ROWS * 2 + 128)

__global__ __launch_bounds__(128) void prep_kernel(
    const float* __restrict__ off,        // (P,V,3)
    const float* __restrict__ base,       // (V,3)
    const float* __restrict__ scales,     // (B,S,1)
    const float* __restrict__ transforms, // (B,S,P,6)
    const float* __restrict__ pw)         // (B,S,P)
{
    extern __shared__ __align__(16) char smem[];
    const int tid = threadIdx.x;

    if (blockIdx.x < NDEF) {
        // ================= defsplit branch =================
        __nv_bfloat16* s_row = (__nv_bfloat16*)smem;        // [VTP][ROWS]
        float* s_base = (float*)(smem + VTP * ROWS * 2);    // [24]
        const int v0 = blockIdx.x * VTP;
        const int nv3 = min(VTP * 3, (V_N - v0) * 3);

        for (int i = tid; i < (VTP * ROWS) / 8; i += 128)
            ((uint4*)s_row)[i] = make_uint4(0, 0, 0, 0);
        if (tid < VTP * 3)
            s_base[tid] = (v0 * 3 + tid < V_N * 3) ? base[v0 * 3 + tid] : 0.f;
        __syncthreads();

        for (int idx = tid; idx < P_N * 12; idx += 128) {
            const int p = idx / 12, q = idx - p * 12;
            const int f0 = 2 * q;
            float e[2];
            if (f0 + 1 < nv3) {
                const float2 d = *(const float2*)(off + ((size_t)p * V_N + v0) * 3 + f0);
                e[0] = d.x; e[1] = d.y;
            } else {
                e[0] = (f0 < nv3) ? off[((size_t)p * V_N + v0) * 3 + f0] : 0.f;
                e[1] = 0.f;
            }
            #pragma unroll
            for (int t = 0; t < 2; ++t) {
                const int f = f0 + t;
                const int vl = f / 3, j = f - 3 * vl;
                const int k = p * 3 + j;
                const float d = e[t] + s_base[f];
                const __nv_bfloat16 hi = __float2bfloat16(d);
                const __nv_bfloat16 lo = __float2bfloat16(d - __bfloat162float(hi));
                __nv_bfloat16* row = s_row + vl * ROWS;
                row[k] = hi; row[192 + k] = lo; row[384 + k] = hi;
            }
        }
        if (tid < VTP) {
            s_row[tid * ROWS + 576] = __float2bfloat16(1.0f);
            s_row[tid * ROWS + 577] = __float2bfloat16(1.0f);
        }
        __syncthreads();

        for (int i = tid; i < VTP * 80; i += 128) {
            const int row = i / 80, u = i - row * 80;
            *(uint4*)(g_def + (size_t)(v0 + row) * KP + u * 8) =
                ((const uint4*)(s_row + row * ROWS))[u];
        }
    } else {
        // ================= rot branch (2 bs per block) =================
        const int bs = (blockIdx.x - NDEF) * 2 + (tid >> 6);
        const int p  = tid & 63;

        const float* t = transforms + ((size_t)bs * P_N + p) * 6;
        const float w  = pw[bs * P_N + p];
        const float ws = w * scales[bs];

        float sx, cx, sy, cy, sz, cz;
        sincosf(t[3], &sx, &cx);
        sincosf(t[4], &sy, &cy);
        sincosf(t[5], &sz, &cz);

        float m[9];
        m[0] = cy*cz;            m[1] = -cy*sz;           m[2] = sy;
        m[3] = cx*sz + sx*sy*cz; m[4] = cx*cz - sx*sy*sz; m[5] = -sx*cy;
        m[6] = sx*sz - cx*sy*cz; m[7] = sx*cz + cx*sy*sz; m[8] = cx*cy;

        #pragma unroll
        for (int i = 0; i < 3; ++i) {
            __nv_bfloat16* row = g_B + ((size_t)i * B_S + bs) * KP;
            #pragma unroll
            for (int j = 0; j < 3; ++j) {
                const float val = m[i * 3 + j] * ws;
                const __nv_bfloat16 hi = __float2bfloat16(val);
                const __nv_bfloat16 lo = __float2bfloat16(val - __bfloat162float(hi));
                const int k = p * 3 + j;
                row[k] = hi; row[192 + k] = hi; row[384 + k] = lo;
            }
        }

        float* red = (float*)smem;   // [128][4]
        red[tid * 4 + 0] = w * t[0];
        red[tid * 4 + 1] = w * t[1];
        red[tid * 4 + 2] = w * t[2];
        __syncthreads();
        if (p < 3) {
            const int b0 = (tid >> 6) * 64;
            float s = 0.f;
            for (int q = 0; q < 64; ++q) s += red[(b0 + q) * 4 + p];
            const __nv_bfloat16 hi = __float2bfloat16(s);
            const __nv_bfloat16 lo = __float2bfloat16(s - __bfloat162float(hi));
            __nv_bfloat16* row = g_B + ((size_t)p * B_S + bs) * KP;
            row[576] = hi; row[577] = lo;
        }
    }
}

// ---------------------------------------------------------------------------
// Main GEMM via mma.sync: per-CTA 128x128, K'=640. Grid (21, 6) = 126 CTAs
// -> exactly one CTA per SM (balanced, no double-loaded SMs). 512 threads,
// 4x4 warp grid of 32x32 warp tiles. 3-stage cp.async pipeline.
// ---------------------------------------------------------------------------
#define STG_SZ    32768u                      // A 16KB + B 16KB per stage
#define SM_A(b)   ((b) * STG_SZ)
#define SM_B(b)   ((b) * STG_SZ + 16384u)
#define SMEM_BYTES (3 * 32768)                // 98,304

__global__ __launch_bounds__(512, 1) void mesh_gemm_kernel(float* __restrict__ out)
{
    extern __shared__ __align__(1024) char smem[];
    const uint32_t sbase = smem_u32(smem);
    const int tid  = threadIdx.x;
    const int lane = tid & 31;
    const int warp = tid >> 5;                 // 0..15
    const int v0   = blockIdx.x * M_T;
    const int nb   = blockIdx.y;
    const int i_   = nb >> 1;                  // output component (0..2)
    const int bs0  = (nb & 1) * N_T;           // bs half base
    const int bRow0 = i_ * B_S + bs0;          // g_B row base

    const int wm = warp & 3;                   // warp row (4) -> 32 v
    const int wn = warp >> 2;                  // warp col (4) -> 32 n

    const int rowA  = wm * 32 + (lane & 7) + ((lane >> 3) & 1) * 8;
    const int kselA = ((lane >> 4) & 1) * 16;
    const int rowB  = wn * 32 + ((lane >> 4) & 1) * 8 + (lane & 7);
    const int kselB = ((lane >> 3) & 1) * 16;

    // staging coords: A 1024 uint4, B 1024 uint4; 2 each per thread
    const int sRow = tid >> 3, sU = (tid & 7) * 16;

    float acc[2][4][4];
    #pragma unroll
    for (int mt = 0; mt < 2; ++mt)
        #pragma unroll
        for (int nt = 0; nt < 4; ++nt)
            #pragma unroll
            for (int e = 0; e < 4; ++e) acc[mt][nt][e] = 0.f;

    auto stage_cp = [&](int c, int b) {
        const uint32_t sA = sbase + SM_A(b), sB = sbase + SM_B(b);
        const __nv_bfloat16* gA = g_def + (size_t)v0 * KP + c * 64;
        const __nv_bfloat16* gB = g_B + (size_t)bRow0 * KP + c * 64;
        #pragma unroll
        for (int it = 0; it < 2; ++it) {
            const int row = sRow + it * 64;
            CP16(sA + sw128(row * 128 + sU), gA + (size_t)row * KP + sU / 2);
            CP16(sB + sw128(row * 128 + sU), gB + (size_t)row * KP + sU / 2);
        }
    };
    auto compute = [&](int b) {
        const uint32_t sA = sbase + SM_A(b);
        const uint32_t sB = sbase + SM_B(b);
        #pragma unroll
        for (int ks = 0; ks < 4; ++ks) {
            uint32_t a0[4], a1[4], q0[4], q1[4];
            LDSM4(a0, sA + sw128(rowA * 128 + ks * 32 + kselA));
            LDSM4(a1, sA + sw128((rowA + 16) * 128 + ks * 32 + kselA));
            LDSM4(q0, sB + sw128(rowB * 128 + ks * 32 + kselB));
            LDSM4(q1, sB + sw128((rowB + 16) * 128 + ks * 32 + kselB));
            MMA(acc[0][0], a0, q0[0], q0[1]);  MMA(acc[0][1], a0, q0[2], q0[3]);
            MMA(acc[0][2], a0, q1[0], q1[1]);  MMA(acc[0][3], a0, q1[2], q1[3]);
            MMA(acc[1][0], a1, q0[0], q0[1]);  MMA(acc[1][1], a1, q0[2], q0[3]);
            MMA(acc[1][2], a1, q1[0], q1[1]);  MMA(acc[1][3], a1, q1[2], q1[3]);
        }
    };

    stage_cp(0, 0); CP_COMMIT();
    stage_cp(1, 1); CP_COMMIT();

    for (int c = 0; c < NCH; ++c) {
        CP_WAIT1();
        __syncthreads();
        compute(c % 3);
        if (c + 2 < NCH) stage_cp(c + 2, (c + 2) % 3);
        CP_COMMIT();
    }

    // ---- epilogue: scatter stores ----
    const int g  = lane >> 2;
    const int cq = lane & 3;
    #pragma unroll
    for (int mt = 0; mt < 2; ++mt) {
        const int vA = v0 + wm * 32 + mt * 16 + g;
        const int vB = vA + 8;
        #pragma unroll
        for (int nt = 0; nt < 4; ++nt) {
            const int bs = bs0 + wn * 32 + nt * 8 + 2 * cq;
            const size_t r0 = ((size_t)bs * V_N) * 3 + i_;
            const size_t r1 = ((size_t)(bs + 1) * V_N) * 3 + i_;
            if (vA < V_N) {
                out[r0 + (size_t)vA * 3] = acc[mt][nt][0];
                out[r1 + (size_t)vA * 3] = acc[mt][nt][1];
            }
            if (vB < V_N) {
                out[r0 + (size_t)vB * 3] = acc[mt][nt][2];
                out[r1 + (size_t)vB * 3] = acc[mt][nt][3];
            }
        }
    }
}

// ---------------------------------------------------------------------------
extern "C" void kernel_launch(void* const* d_in, const int* in_sizes, int n_in,
                              void* d_out, int out_size)
{
    (void)in_sizes; (void)n_in; (void)out_size;
    const float* scales     = (const float*)d_in[0];  // (B,S,1)
    const float* transforms = (const float*)d_in[1];  // (B,S,P,6)
    const float* pw         = (const float*)d_in[2];  // (B,S,P)
    const float* off        = (const float*)d_in[3];  // (P,V,3)
    const float* base       = (const float*)d_in[4];  // (V,3)
    float* out = (float*)d_out;

    cudaFuncSetAttribute(prep_kernel,
                         cudaFuncAttributeMaxDynamicSharedMemorySize, PREP_SMEM);
    prep_kernel<<<NDEF + NROT, 128, PREP_SMEM>>>(off, base, scales, transforms, pw);

    cudaFuncSetAttribute(mesh_gemm_kernel,
                         cudaFuncAttributeMaxDynamicSharedMemorySize, SMEM_BYTES);
    dim3 grid((V_N + M_T - 1) / M_T, 6);   // (21, 6) = 126 CTAs, 1 per SM
    mesh_gemm_kernel<<<grid, 512, SMEM_BYTES>>>(out);
}

// round 14
// speedup vs baseline: 1.5108x; 1.0879x over previous
#include <cuda_runtime.h>
#include <cuda_fp16.h>
#include <cstdint>

#define B_S   256
#define P_N   64
#define V_N   2562
#define VPAD  2688          // 21*128, zero-padded tail rows
#define KP    256           // K' = 192 (fp16 hi) + 64 (trans chunk, cols 192/193)
#define NCH   4             // K chunks of 64 fp16 (128B rows)
#define M_T   128           // v rows per CTA
#define N_T   128           // n cols per CTA (one i, half the bs)

#define VTP   16            // defsplit v-tile
#define NDEF  161           // ceil(2562/16)
#define NROT  128           // rot blocks (2 bs each)
#define ROWS2 264           // padded smem row stride (fp16) for prep staging

// ---- scratch (zero-initialized device globals; no runtime alloc) ----
__device__ __align__(16) __half g_def[(size_t)VPAD * KP];     // ~1.4MB
__device__ __align__(16) __half g_B[(size_t)3 * B_S * KP];    // ~0.4MB

__device__ __forceinline__ uint32_t smem_u32(const void* p) {
    uint32_t a;
    asm("{ .reg .u64 t; cvta.to.shared.u64 t, %1; cvt.u32.u64 %0, t; }" : "=r"(a) : "l"(p));
    return a;
}
__device__ __forceinline__ uint32_t sw128(uint32_t x) { return x ^ ((x >> 3) & 0x70); }

#define CP16(dst, src) \
    asm volatile("cp.async.cg.shared.global [%0], [%1], 16;" :: "r"(dst), "l"(src))
#define CP_COMMIT() asm volatile("cp.async.commit_group;" ::: "memory")
#define CP_WAIT1()  asm volatile("cp.async.wait_group 1;" ::: "memory")

#define LDSM4(r, addr) \
    asm volatile("ldmatrix.sync.aligned.m8n8.x4.shared.b16 {%0,%1,%2,%3}, [%4];" \
        : "=r"((r)[0]), "=r"((r)[1]), "=r"((r)[2]), "=r"((r)[3]) : "r"(addr))

#define MMA(d, a, b0, b1) \
    asm volatile("mma.sync.aligned.m16n8k16.row.col.f32.f16.f16.f32 " \
        "{%0,%1,%2,%3}, {%4,%5,%6,%7}, {%8,%9}, {%0,%1,%2,%3};" \
        : "+f"((d)[0]), "+f"((d)[1]), "+f"((d)[2]), "+f"((d)[3]) \
        : "r"((a)[0]), "r"((a)[1]), "r"((a)[2]), "r"((a)[3]), "r"(b0), "r"(b1))

// ---------------------------------------------------------------------------
// Fused prep. Blocks [0, NDEF): defsplit (v-tile of 16, coalesced transpose).
// Blocks [NDEF, NDEF+NROT): rot — 2 bs per block, builds B-hat rows.
// ---------------------------------------------------------------------------
#define PREP_SMEM (VTP * ROWS2 * 2 + 256)

__global__ __launch_bounds__(128) void prep_kernel(
    const float* __restrict__ off,        // (P,V,3)
    const float* __restrict__ base,       // (V,3)
    const float* __restrict__ scales,     // (B,S,1)
    const float* __restrict__ transforms, // (B,S,P,6)
    const float* __restrict__ pw)         // (B,S,P)
{
    extern __shared__ __align__(16) char smem[];
    const int tid = threadIdx.x;

    if (blockIdx.x < NDEF) {
        // ================= defsplit branch =================
        __half* s_row = (__half*)smem;                      // [VTP][ROWS2]
        float* s_base = (float*)(smem + VTP * ROWS2 * 2);   // [48]
        const int v0 = blockIdx.x * VTP;
        const int nv3 = min(VTP * 3, (V_N - v0) * 3);

        for (int i = tid; i < (VTP * ROWS2) / 8; i += 128)
            ((uint4*)s_row)[i] = make_uint4(0, 0, 0, 0);
        if (tid < VTP * 3)
            s_base[tid] = (v0 * 3 + tid < V_N * 3) ? base[v0 * 3 + tid] : 0.f;
        __syncthreads();

        // coalesced read + transpose: 64 p x 24 float2 (48 floats = 16v x 3j)
        for (int idx = tid; idx < P_N * 24; idx += 128) {
            const int p = idx / 24, q = idx - p * 24;
            const int f0 = 2 * q;
            float e[2];
            if (f0 + 1 < nv3) {
                const float2 d = *(const float2*)(off + ((size_t)p * V_N + v0) * 3 + f0);
                e[0] = d.x; e[1] = d.y;
            } else {
                e[0] = (f0 < nv3) ? off[((size_t)p * V_N + v0) * 3 + f0] : 0.f;
                e[1] = 0.f;
            }
            #pragma unroll
            for (int t = 0; t < 2; ++t) {
                const int f = f0 + t;
                const int vl = f / 3, j = f - 3 * vl;
                s_row[vl * ROWS2 + p * 3 + j] = __float2half(e[t] + s_base[f]);
            }
        }
        if (tid < VTP) {
            s_row[tid * ROWS2 + 192] = __float2half(1.0f);
            s_row[tid * ROWS2 + 193] = __float2half(1.0f);
        }
        __syncthreads();

        // coalesced write-out: 16 rows x 32 uint4
        for (int i = tid; i < VTP * 32; i += 128) {
            const int row = i >> 5, u = i & 31;
            *(uint4*)(g_def + (size_t)(v0 + row) * KP + u * 8) =
                ((const uint4*)(s_row + row * ROWS2))[u];
        }
    } else {
        // ================= rot branch (2 bs per block) =================
        const int bs = (blockIdx.x - NDEF) * 2 + (tid >> 6);
        const int p  = tid & 63;

        const float* t = transforms + ((size_t)bs * P_N + p) * 6;
        const float w  = pw[bs * P_N + p];
        const float ws = w * scales[bs];

        float sx, cx, sy, cy, sz, cz;
        sincosf(t[3], &sx, &cx);
        sincosf(t[4], &sy, &cy);
        sincosf(t[5], &sz, &cz);

        float m[9];
        m[0] = cy*cz;            m[1] = -cy*sz;           m[2] = sy;
        m[3] = cx*sz + sx*sy*cz; m[4] = cx*cz - sx*sy*sz; m[5] = -sx*cy;
        m[6] = sx*sz - cx*sy*cz; m[7] = sx*cz + cx*sy*sz; m[8] = cx*cy;

        #pragma unroll
        for (int i = 0; i < 3; ++i) {
            __half* row = g_B + ((size_t)i * B_S + bs) * KP;
            #pragma unroll
            for (int j = 0; j < 3; ++j)
                row[p * 3 + j] = __float2half(m[i * 3 + j] * ws);
        }

        float* red = (float*)smem;   // [128][4]
        red[tid * 4 + 0] = w * t[0];
        red[tid * 4 + 1] = w * t[1];
        red[tid * 4 + 2] = w * t[2];
        __syncthreads();
        if (p < 3) {
            const int b0 = (tid >> 6) * 64;
            float s = 0.f;
            for (int q = 0; q < 64; ++q) s += red[(b0 + q) * 4 + p];
            const __half hi = __float2half(s);
            const __half lo = __float2half(s - __half2float(hi));
            __half* row = g_B + ((size_t)p * B_S + bs) * KP;
            row[192] = hi; row[193] = lo;
        }
    }
}

// ---------------------------------------------------------------------------
// Main GEMM via mma.sync (f16): per-CTA 128x128, K'=256 (4 chunks).
// Grid (21, 6) = 126 CTAs -> one per SM. 512 threads, 4x4 warp grid of
// 32x32 warp tiles. 3-stage cp.async pipeline.
// ---------------------------------------------------------------------------
#define STG_SZ    32768u                      // A 16KB + B 16KB per stage
#define SM_A(b)   ((b) * STG_SZ)
#define SM_B(b)   ((b) * STG_SZ + 16384u)
#define SMEM_BYTES (3 * 32768)                // 98,304

__global__ __launch_bounds__(512, 1) void mesh_gemm_kernel(float* __restrict__ out)
{
    extern __shared__ __align__(1024) char smem[];
    const uint32_t sbase = smem_u32(smem);
    const int tid  = threadIdx.x;
    const int lane = tid & 31;
    const int warp = tid >> 5;                 // 0..15
    const int v0   = blockIdx.x * M_T;
    const int nb   = blockIdx.y;
    const int i_   = nb >> 1;                  // output component (0..2)
    const int bs0  = (nb & 1) * N_T;           // bs half base
    const int bRow0 = i_ * B_S + bs0;          // g_B row base

    const int wm = warp & 3;                   // warp row (4) -> 32 v
    const int wn = warp >> 2;                  // warp col (4) -> 32 n

    const int rowA  = wm * 32 + (lane & 7) + ((lane >> 3) & 1) * 8;
    const int kselA = ((lane >> 4) & 1) * 16;
    const int rowB  = wn * 32 + ((lane >> 4) & 1) * 8 + (lane & 7);
    const int kselB = ((lane >> 3) & 1) * 16;

    const int sRow = tid >> 3, sU = (tid & 7) * 16;

    float acc[2][4][4];
    #pragma unroll
    for (int mt = 0; mt < 2; ++mt)
        #pragma unroll
        for (int nt = 0; nt < 4; ++nt)
            #pragma unroll
            for (int e = 0; e < 4; ++e) acc[mt][nt][e] = 0.f;

    auto stage_cp = [&](int c, int b) {
        const uint32_t sA = sbase + SM_A(b), sB = sbase + SM_B(b);
        const __half* gA = g_def + (size_t)v0 * KP + c * 64;
        const __half* gB = g_B + (size_t)bRow0 * KP + c * 64;
        #pragma unroll
        for (int it = 0; it < 2; ++it) {
            const int row = sRow + it * 64;
            CP16(sA + sw128(row * 128 + sU), gA + (size_t)row * KP + sU / 2);
            CP16(sB + sw128(row * 128 + sU), gB + (size_t)row * KP + sU / 2);
        }
    };
    auto compute = [&](int b) {
        const uint32_t sA = sbase + SM_A(b);
        const uint32_t sB = sbase + SM_B(b);
        #pragma unroll
        for (int ks = 0; ks < 4; ++ks) {
            uint32_t a0[4], a1[4], q0[4], q1[4];
            LDSM4(a0, sA + sw128(rowA * 128 + ks * 32 + kselA));
            LDSM4(a1, sA + sw128((rowA + 16) * 128 + ks * 32 + kselA));
            LDSM4(q0, sB + sw128(rowB * 128 + ks * 32 + kselB));
            LDSM4(q1, sB + sw128((rowB + 16) * 128 + ks * 32 + kselB));
            MMA(acc[0][0], a0, q0[0], q0[1]);  MMA(acc[0][1], a0, q0[2], q0[3]);
            MMA(acc[0][2], a0, q1[0], q1[1]);  MMA(acc[0][3], a0, q1[2], q1[3]);
            MMA(acc[1][0], a1, q0[0], q0[1]);  MMA(acc[1][1], a1, q0[2], q0[3]);
            MMA(acc[1][2], a1, q1[0], q1[1]);  MMA(acc[1][3], a1, q1[2], q1[3]);
        }
    };

    stage_cp(0, 0); CP_COMMIT();
    stage_cp(1, 1); CP_COMMIT();

    for (int c = 0; c < NCH; ++c) {
        CP_WAIT1();
        __syncthreads();
        compute(c % 3);
        if (c + 2 < NCH) stage_cp(c + 2, (c + 2) % 3);
        CP_COMMIT();
    }

    // ---- epilogue: scatter stores ----
    const int g  = lane >> 2;
    const int cq = lane & 3;
    #pragma unroll
    for (int mt = 0; mt < 2; ++mt) {
        const int vA = v0 + wm * 32 + mt * 16 + g;
        const int vB = vA + 8;
        #pragma unroll
        for (int nt = 0; nt < 4; ++nt) {
            const int bs = bs0 + wn * 32 + nt * 8 + 2 * cq;
            const size_t r0 = ((size_t)bs * V_N) * 3 + i_;
            const size_t r1 = ((size_t)(bs + 1) * V_N) * 3 + i_;
            if (vA < V_N) {
                out[r0 + (size_t)vA * 3] = acc[mt][nt][0];
                out[r1 + (size_t)vA * 3] = acc[mt][nt][1];
            }
            if (vB < V_N) {
                out[r0 + (size_t)vB * 3] = acc[mt][nt][2];
                out[r1 + (size_t)vB * 3] = acc[mt][nt][3];
            }
        }
    }
}

// ---------------------------------------------------------------------------
extern "C" void kernel_launch(void* const* d_in, const int* in_sizes, int n_in,
                              void* d_out, int out_size)
{
    (void)in_sizes; (void)n_in; (void)out_size;
    const float* scales     = (const float*)d_in[0];  // (B,S,1)
    const float* transforms = (const float*)d_in[1];  // (B,S,P,6)
    const float* pw         = (const float*)d_in[2];  // (B,S,P)
    const float* off        = (const float*)d_in[3];  // (P,V,3)
    const float* base       = (const float*)d_in[4];  // (V,3)
    float* out = (float*)d_out;

    cudaFuncSetAttribute(prep_kernel,
                         cudaFuncAttributeMaxDynamicSharedMemorySize, PREP_SMEM);
    prep_kernel<<<NDEF + NROT, 128, PREP_SMEM>>>(off, base, scales, transforms, pw);

    cudaFuncSetAttribute(mesh_gemm_kernel,
                         cudaFuncAttributeMaxDynamicSharedMemorySize, SMEM_BYTES);
    dim3 grid((V_N + M_T - 1) / M_T, 6);   // (21, 6) = 126 CTAs, 1 per SM
    mesh_gemm_kernel<<<grid, 512, SMEM_BYTES>>>(out);
}